// round 14
// baseline (speedup 1.0000x reference)
#include <cuda_runtime.h>
#include <math.h>
#include <float.h>
#include <stdint.h>

// Problem constants (from reference): B=8, Z=4, X=32, Y=32, N=4096
#define NPTS   4096
#define NB     8
#define THREADS 512
#define NWARP  (THREADS / 32)
#define NITER  (NPTS / THREADS)   // 8
#define MAXKEEP 32
#define CUT2   4.0f               // sqrt(ss) < 2  <=>  ss < 4 (exact)

#define CHUNK  1024               // points per staging unit
#define NCHUNK (NPTS / CHUNK)     // 4
#define NUNITS (2 * NCHUNK)       // 8: pred c0..c3, targ c0..c3 interleaved
#define STG_FLOATS (CHUNK * 10)   // 10240 floats = 40960 bytes per unit
#define STG_BYTES (STG_FLOATS * 4)

// smem: 8 point arrays + 2 staging slots + warp scratch + kept arrays
#define SMEM_BYTES ((8 * NPTS + 2 * STG_FLOATS + 2 * NWARP + 4 * MAXKEEP) * 4)

__device__ __forceinline__ uint32_t smem_u32(const void* p) {
    uint32_t a;
    asm("{ .reg .u64 t; cvta.to.shared.u64 t, %1; cvt.u32.u64 %0, t; }"
        : "=r"(a) : "l"(p));
    return a;
}

__device__ __forceinline__ void mbar_init(uint32_t mbar, uint32_t count) {
    asm volatile("mbarrier.init.shared.b64 [%0], %1;" :: "r"(mbar), "r"(count) : "memory");
}
__device__ __forceinline__ void mbar_expect_tx(uint32_t mbar, uint32_t bytes) {
    asm volatile("mbarrier.arrive.expect_tx.shared.b64 _, [%0], %1;"
                 :: "r"(mbar), "r"(bytes) : "memory");
}
__device__ __forceinline__ void bulk_copy_g2s(uint32_t dst_smem, const void* src,
                                              uint32_t bytes, uint32_t mbar) {
    asm volatile("cp.async.bulk.shared::cta.global.mbarrier::complete_tx::bytes "
                 "[%0], [%1], %2, [%3];"
                 :: "r"(dst_smem), "l"(src), "r"(bytes), "r"(mbar) : "memory");
}
__device__ __forceinline__ void mbar_wait_parity(uint32_t mbar, uint32_t parity) {
    asm volatile(
        "{\n\t"
        ".reg .pred P;\n\t"
        "WAIT_%=:\n\t"
        "mbarrier.try_wait.parity.acquire.cta.shared::cta.b64 P, [%0], %1, 0x989680;\n\t"
        "@P bra.uni DONE_%=;\n\t"
        "bra.uni WAIT_%=;\n\t"
        "DONE_%=:\n\t"
        "}"
        :: "r"(mbar), "r"(parity) : "memory");
}

__device__ __forceinline__ float row_angle(float ax, float ay, float az,
                                           float bx, float by, float bz) {
    float na = sqrtf(ax * ax + ay * ay + az * az);
    float nb = sqrtf(bx * bx + by * by + bz * bz);
    float c = (ax * bx + ay * by + az * bz) / (na * nb);
    c = fminf(1.0f, fmaxf(-1.0f, c));
    return (acosf(c) / 3.14159265358979323846f) * 180.0f;
}

__global__ __launch_bounds__(THREADS, 1)
void mol_kernel(const float* __restrict__ pred,
                const float* __restrict__ targ,
                float* __restrict__ out) {
    extern __shared__ float sm[];
    float* s_conf = sm;                 // [NPTS] pred conf (raw, -FLT_MAX = inactive)
    float* s_p0 = s_conf + NPTS;        // [NPTS] pred pos normalized
    float* s_p1 = s_p0 + NPTS;
    float* s_p2 = s_p1 + NPTS;
    float* s_t0 = s_p2 + NPTS;          // [NPTS] target pos in REAL coords
    float* s_t1 = s_t0 + NPTS;
    float* s_t2 = s_t1 + NPTS;
    float* s_tc = s_t2 + NPTS;          // [NPTS] target conf
    float* stage0 = s_tc + NPTS;        // [STG_FLOATS] staging slot 0
    float* stage1 = stage0 + STG_FLOATS;// [STG_FLOATS] staging slot 1
    float* wv = stage1 + STG_FLOATS;    // [NWARP]
    int* wi = (int*)(wv + NWARP);       // [NWARP]
    float* kx = (float*)(wi + NWARP);   // kept point normalized coords
    float* ky = kx + MAXKEEP;
    float* kz = ky + MAXKEEP;
    int* kid = (int*)(kz + MAXKEEP);    // kept original indices

    __shared__ alignas(8) unsigned long long mbar_st[2];
    __shared__ int sK, sSel, sTP, sNTG;
    __shared__ float sAng;
    __shared__ float selp[3];

    const int tid = threadIdx.x;
    const int lane = tid & 31;
    const int warp = tid >> 5;
    const int b = blockIdx.x;
    const float* P = pred + (long long)b * NPTS * 10;
    const float* T = targ + (long long)b * NPTS * 10;

    const uint32_t mb0 = smem_u32(&mbar_st[0]);
    const uint32_t mb1 = smem_u32(&mbar_st[1]);
    const uint32_t stg0 = smem_u32(stage0);
    const uint32_t stg1 = smem_u32(stage1);

    // ---- Phase 1: TMA bulk-copy staging ring + parse ----
    // unit u: tensor = u&1 (0=pred,1=targ), chunk = u>>1; slot = u&1... we map
    // units as (pred c, targ c) pairs: unit u -> tensor u&1, chunk u>>1.
    if (tid == 0) {
        mbar_init(mb0, 1);
        mbar_init(mb1, 1);
    }
    __syncthreads();
    if (tid == 0) {
        // issue units 0 (pred c0 -> slot0) and 1 (targ c0 -> slot1)
        mbar_expect_tx(mb0, STG_BYTES);
        bulk_copy_g2s(stg0, P, STG_BYTES, mb0);
        mbar_expect_tx(mb1, STG_BYTES);
        bulk_copy_g2s(stg1, T, STG_BYTES, mb1);
    }

    int cnt = 0;
    #pragma unroll
    for (int u = 0; u < NUNITS; u++) {
        const int slot = u & 1;
        const int phase = (u >> 1) & 1;        // per-slot use count parity
        const int tensor = u & 1;              // 0 = pred, 1 = targ
        const int c = u >> 1;
        mbar_wait_parity(slot ? mb1 : mb0, phase);
        float* S = slot ? stage1 : stage0;
        #pragma unroll
        for (int k = 0; k < CHUNK / THREADS; k++) {
            int loc = tid + k * THREADS;
            int n = c * CHUNK + loc;
            const float* q = S + loc * 10;     // 40B pitch -> 8B aligned in smem
            float2 f01 = *(const float2*)q;
            float2 f23 = *(const float2*)(q + 2);
            float z = (float)(n >> 10), x = (float)((n >> 5) & 31), y = (float)(n & 31);
            if (tensor == 0) {
                // sigmoid(c) > 0.5 <=> c > 0 (exact); /4,/32 exact pow2 mults
                s_conf[n] = (f01.x > 0.0f) ? f01.x : -FLT_MAX;
                s_p0[n] = (f01.y + z) * 0.25f;
                s_p1[n] = (f23.x + x) * 0.03125f;
                s_p2[n] = (f23.y + y) * 0.03125f;
            } else {
                s_tc[n] = f01.x;
                cnt += (f01.x > 0.5f) ? 1 : 0;
                s_t0[n] = ((f01.y + z) * 0.25f) * 25.0f;   // real coords (×25,25,4)
                s_t1[n] = ((f23.x + x) * 0.03125f) * 25.0f;
                s_t2[n] = ((f23.y + y) * 0.03125f) * 4.0f;
            }
        }
        __syncthreads();                        // all parses done before slot reuse
        if (u + 2 < NUNITS && tid == 0) {
            int u2 = u + 2;
            const float* g = ((u2 & 1) ? T : P) + (u2 >> 1) * CHUNK * 10;
            uint32_t mb = slot ? mb1 : mb0;
            mbar_expect_tx(mb, STG_BYTES);
            bulk_copy_g2s(slot ? stg1 : stg0, g, STG_BYTES, mb);
        }
    }

    // target count (folded reduce)
    #pragma unroll
    for (int o = 16; o; o >>= 1) cnt += __shfl_down_sync(0xffffffffu, cnt, o);
    if (lane == 0) wi[warp] = cnt;
    if (tid == 0) { sK = 0; sTP = 0; sAng = 0.0f; }
    __syncthreads();
    if (tid == 0) {
        int s = 0;
        for (int w = 0; w < NWARP; w++) s += wi[w];
        sNTG = s;
    }
    __syncthreads();

    // ---- Phase 2: round-based greedy NMS (R8 champion structure, untouched) ----
    for (;;) {
        float bv = -FLT_MAX;
        int bi = 0x7fffffff;
        #pragma unroll
        for (int j = 0; j < NITER; j++) {
            int n = tid + j * THREADS;
            float v = s_conf[n];
            if (v > bv) { bv = v; bi = n; }   // ascending n => ties keep lowest idx
        }
        #pragma unroll
        for (int o = 16; o; o >>= 1) {
            float v2 = __shfl_down_sync(0xffffffffu, bv, o);
            int i2 = __shfl_down_sync(0xffffffffu, bi, o);
            if (v2 > bv || (v2 == bv && i2 < bi)) { bv = v2; bi = i2; }
        }
        if (lane == 0) { wv[warp] = bv; wi[warp] = bi; }
        __syncthreads();
        if (warp == 0) {
            float v = (lane < NWARP) ? wv[lane] : -FLT_MAX;
            int i = (lane < NWARP) ? wi[lane] : 0x7fffffff;
            #pragma unroll
            for (int o = 8; o; o >>= 1) {
                float v2 = __shfl_down_sync(0xffffffffu, v, o);
                int i2 = __shfl_down_sync(0xffffffffu, i, o);
                if (v2 > v || (v2 == v && i2 < i)) { v = v2; i = i2; }
            }
            if (lane == 0) {
                if (v == -FLT_MAX || sK >= MAXKEEP) {
                    sSel = -1;
                } else {
                    sSel = i;
                    int K = sK;
                    kx[K] = s_p0[i]; ky[K] = s_p1[i]; kz[K] = s_p2[i]; kid[K] = i;
                    selp[0] = s_p0[i]; selp[1] = s_p1[i]; selp[2] = s_p2[i];
                    sK = K + 1;
                }
            }
        }
        __syncthreads();
        if (sSel < 0) break;
        float c0 = selp[0], c1 = selp[1], c2 = selp[2];
        #pragma unroll
        for (int j = 0; j < NITER; j++) {
            int n = tid + j * THREADS;
            if (s_conf[n] != -FLT_MAX) {
                float d0 = s_p0[n] - c0, d1 = s_p1[n] - c1, d2 = s_p2[n] - c2;
                float ss = (d0 * d0 + d1 * d1) + d2 * d2;
                if (ss < CUT2) s_conf[n] = -FLT_MAX;
            }
        }
        __syncthreads();
    }

    // ---- Phase 3: per kept pred, first in-range active target; angles (R8) ----
    const int K = sK;
    for (int k = 0; k < K; k++) {
        float q0 = kx[k] * 25.0f, q1 = ky[k] * 25.0f, q2 = kz[k] * 4.0f;
        int best = 0x7fffffff;
        #pragma unroll
        for (int j = 0; j < NITER; j++) {
            int t = tid + j * THREADS;
            if (s_tc[t] > 0.5f) {
                float d0 = s_t0[t] - q0, d1 = s_t1[t] - q1, d2 = s_t2[t] - q2;
                float ss = (d0 * d0 + d1 * d1) + d2 * d2;
                if (ss < CUT2 && t < best) best = t;
            }
        }
        #pragma unroll
        for (int o = 16; o; o >>= 1) {
            int v2 = __shfl_down_sync(0xffffffffu, best, o);
            if (v2 < best) best = v2;
        }
        if (lane == 0) wi[warp] = best;
        __syncthreads();
        if (tid == 0) {
            int bmin = 0x7fffffff;
            for (int w = 0; w < NWARP; w++) if (wi[w] < bmin) bmin = wi[w];
            if (bmin != 0x7fffffff) {
                sTP += 1;
                int i = kid[k];
                const float* p = P + (long long)i * 10;
                const float* t = T + (long long)bmin * 10;
                float ax = p[4], ay = p[5], az = p[6];
                float bx = p[7], by = p[8], bz = p[9];
                float cx = ay * bz - az * by;
                float cy = az * bx - ax * bz;
                float cz = ax * by - ay * bx;
                float tax = t[4], tay = t[5], taz = t[6];
                float tbx = t[7], tby = t[8], tbz = t[9];
                float tcx = tay * tbz - taz * tby;
                float tcy = taz * tbx - tax * tbz;
                float tcz = tax * tby - tay * tbx;
                sAng += row_angle(ax, ay, az, tax, tay, taz)
                      + row_angle(bx, by, bz, tbx, tby, tbz)
                      + row_angle(cx, cy, cz, tcx, tcy, tcz);
            }
        }
        __syncthreads();
    }

    // ---- Phase 4: write outputs ----
    if (tid == 0) {
        float tp = (float)sTP;
        out[b * 3 + 0] = tp;
        out[b * 3 + 1] = (float)K - tp;
        out[b * 3 + 2] = (float)sNTG - tp;
        out[3 * NB + b] = (sTP > 0) ? (sAng / (3.0f * tp)) : 0.0f;
    }
}

extern "C" void kernel_launch(void* const* d_in, const int* in_sizes, int n_in,
                              void* d_out, int out_size) {
    const float* pred = (const float*)d_in[0];
    const float* targ = (const float*)d_in[1];
    float* out = (float*)d_out;
    cudaFuncSetAttribute(mol_kernel, cudaFuncAttributeMaxDynamicSharedMemorySize,
                         SMEM_BYTES);
    mol_kernel<<<NB, THREADS, SMEM_BYTES>>>(pred, targ, out);
}

// round 15
// speedup vs baseline: 1.0179x; 1.0179x over previous
#include <cuda_runtime.h>
#include <math.h>
#include <float.h>
#include <stdint.h>

// Problem constants (from reference): B=8, Z=4, X=32, Y=32, N=4096
#define NPTS   4096
#define NB     8
#define THREADS 512
#define NWARP  (THREADS / 32)
#define NITER  (NPTS / THREADS)   // 8
#define MAXKEEP 128
#define CUT2   4.0f               // sqrt(ss) < 2  <=>  ss < 4 (exact)

#define CHUNK  1024               // points per unit
#define NUNITS 8                  // pred c0..c3 / targ c0..c3 interleaved
#define STG_FLOATS (CHUNK * 10)   // 10240 floats = 40 KB per unit
#define F4_PER_UNIT (STG_FLOATS / 4)      // 2560 float4
#define CP_PER_THREAD (F4_PER_UNIT / THREADS)  // 5

// smem: 8 point arrays + 2 staging slots + warp scratch + kept arrays  (~210 KB)
#define SMEM_BYTES ((8 * NPTS + 2 * STG_FLOATS + 2 * NWARP + 4 * MAXKEEP) * 4)

__device__ __forceinline__ uint32_t smem_u32(const void* p) {
    uint32_t a;
    asm("{ .reg .u64 t; cvta.to.shared.u64 t, %1; cvt.u32.u64 %0, t; }"
        : "=r"(a) : "l"(p));
    return a;
}
__device__ __forceinline__ void cp16(uint32_t dst, const void* src) {
    asm volatile("cp.async.cg.shared.global [%0], [%1], 16;"
                 :: "r"(dst), "l"(src) : "memory");
}
__device__ __forceinline__ void cp_commit() {
    asm volatile("cp.async.commit_group;" ::: "memory");
}
template <int N>
__device__ __forceinline__ void cp_wait() {
    asm volatile("cp.async.wait_group %0;" :: "n"(N) : "memory");
}

__device__ __forceinline__ float row_angle(float ax, float ay, float az,
                                           float bx, float by, float bz) {
    float na = sqrtf(ax * ax + ay * ay + az * az);
    float nb = sqrtf(bx * bx + by * by + bz * bz);
    float c = (ax * bx + ay * by + az * bz) / (na * nb);
    c = fminf(1.0f, fmaxf(-1.0f, c));
    return (acosf(c) / 3.14159265358979323846f) * 180.0f;
}

__global__ __launch_bounds__(THREADS, 1)
void mol_kernel(const float* __restrict__ pred,
                const float* __restrict__ targ,
                float* __restrict__ out) {
    extern __shared__ float sm[];
    float* s_conf = sm;                 // [NPTS] pred conf (raw, -FLT_MAX = inactive)
    float* s_p0 = s_conf + NPTS;        // [NPTS] pred pos normalized
    float* s_p1 = s_p0 + NPTS;
    float* s_p2 = s_p1 + NPTS;
    float* s_t0 = s_p2 + NPTS;          // [NPTS] target pos in REAL coords
    float* s_t1 = s_t0 + NPTS;
    float* s_t2 = s_t1 + NPTS;
    float* s_tc = s_t2 + NPTS;          // [NPTS] target conf
    float* stage0 = s_tc + NPTS;        // [STG_FLOATS] staging slot 0
    float* stage1 = stage0 + STG_FLOATS;// [STG_FLOATS] staging slot 1
    float* wv = stage1 + STG_FLOATS;    // [NWARP]
    int* wi = (int*)(wv + NWARP);       // [NWARP]
    float* kx = (float*)(wi + NWARP);   // kept point normalized coords
    float* ky = kx + MAXKEEP;
    float* kz = ky + MAXKEEP;
    int* kid = (int*)(kz + MAXKEEP);    // kept original indices

    __shared__ int sK, sSel, sTP, sNTG;
    __shared__ float sAng;
    __shared__ float selp[3];

    const int tid = threadIdx.x;
    const int lane = tid & 31;
    const int warp = tid >> 5;
    const int b = blockIdx.x;
    const float* P = pred + (long long)b * NPTS * 10;
    const float* T = targ + (long long)b * NPTS * 10;

    const uint32_t stg_addr[2] = { smem_u32(stage0), smem_u32(stage1) };

    // ---- Phase 1: cp.async staged load (all threads issue; 2-slot ring) ----
    // unit u: tensor = u&1 (0=pred, 1=targ), chunk = u>>1, slot = u&1.
    // prologue: units 0 and 1
    {
        const float* g0 = P;                       // unit 0: pred chunk 0
        const float* g1 = T;                       // unit 1: targ chunk 0
        #pragma unroll
        for (int k = 0; k < CP_PER_THREAD; k++) {
            int idx = tid + k * THREADS;
            cp16(stg_addr[0] + idx * 16, (const char*)g0 + idx * 16);
        }
        cp_commit();
        #pragma unroll
        for (int k = 0; k < CP_PER_THREAD; k++) {
            int idx = tid + k * THREADS;
            cp16(stg_addr[1] + idx * 16, (const char*)g1 + idx * 16);
        }
        cp_commit();
    }

    int cnt = 0;
    #pragma unroll
    for (int u = 0; u < NUNITS; u++) {
        const int slot = u & 1;
        const int tensor = u & 1;
        const int c = u >> 1;
        cp_wait<1>();                    // unit u's group retired (per-thread)
        __syncthreads();                 // everyone's copies of unit u visible
        const float* S = slot ? stage1 : stage0;
        #pragma unroll
        for (int k = 0; k < CHUNK / THREADS; k++) {
            int loc = tid + k * THREADS;
            int n = c * CHUNK + loc;
            const float* q = S + loc * 10;       // 40B pitch, 8B-aligned LDS
            float2 f01 = *(const float2*)q;
            float2 f23 = *(const float2*)(q + 2);
            float z = (float)(n >> 10), x = (float)((n >> 5) & 31), y = (float)(n & 31);
            if (tensor == 0) {
                // sigmoid(c) > 0.5 <=> c > 0 (exact); /4, /32 exact pow2 mults
                s_conf[n] = (f01.x > 0.0f) ? f01.x : -FLT_MAX;
                s_p0[n] = (f01.y + z) * 0.25f;
                s_p1[n] = (f23.x + x) * 0.03125f;
                s_p2[n] = (f23.y + y) * 0.03125f;
            } else {
                s_tc[n] = f01.x;
                cnt += (f01.x > 0.5f) ? 1 : 0;
                s_t0[n] = ((f01.y + z) * 0.25f) * 25.0f;   // real coords (×25,25,4)
                s_t1[n] = ((f23.x + x) * 0.03125f) * 25.0f;
                s_t2[n] = ((f23.y + y) * 0.03125f) * 4.0f;
            }
        }
        __syncthreads();                 // all parses done before slot reuse
        if (u + 2 < NUNITS) {            // issue unit u+2 into this slot
            int u2 = u + 2;
            const float* g = ((u2 & 1) ? T : P) + (u2 >> 1) * STG_FLOATS;
            #pragma unroll
            for (int k = 0; k < CP_PER_THREAD; k++) {
                int idx = tid + k * THREADS;
                cp16(stg_addr[slot] + idx * 16, (const char*)g + idx * 16);
            }
        }
        cp_commit();                     // empty groups keep wait_group counting uniform
    }

    // target count (folded)
    #pragma unroll
    for (int o = 16; o; o >>= 1) cnt += __shfl_down_sync(0xffffffffu, cnt, o);
    if (lane == 0) wi[warp] = cnt;
    if (tid == 0) { sK = 0; sTP = 0; sAng = 0.0f; }
    __syncthreads();
    if (tid == 0) {
        int s = 0;
        for (int w = 0; w < NWARP; w++) s += wi[w];
        sNTG = s;
    }
    __syncthreads();

    // ---- Phase 2: round-based greedy NMS (R8 champion structure, untouched) ----
    for (;;) {
        float bv = -FLT_MAX;
        int bi = 0x7fffffff;
        #pragma unroll
        for (int j = 0; j < NITER; j++) {
            int n = tid + j * THREADS;
            float v = s_conf[n];
            if (v > bv) { bv = v; bi = n; }   // ascending n => ties keep lowest idx
        }
        #pragma unroll
        for (int o = 16; o; o >>= 1) {
            float v2 = __shfl_down_sync(0xffffffffu, bv, o);
            int i2 = __shfl_down_sync(0xffffffffu, bi, o);
            if (v2 > bv || (v2 == bv && i2 < bi)) { bv = v2; bi = i2; }
        }
        if (lane == 0) { wv[warp] = bv; wi[warp] = bi; }
        __syncthreads();
        if (warp == 0) {
            float v = (lane < NWARP) ? wv[lane] : -FLT_MAX;
            int i = (lane < NWARP) ? wi[lane] : 0x7fffffff;
            #pragma unroll
            for (int o = 8; o; o >>= 1) {
                float v2 = __shfl_down_sync(0xffffffffu, v, o);
                int i2 = __shfl_down_sync(0xffffffffu, i, o);
                if (v2 > v || (v2 == v && i2 < i)) { v = v2; i = i2; }
            }
            if (lane == 0) {
                if (v == -FLT_MAX || sK >= MAXKEEP) {
                    sSel = -1;
                } else {
                    sSel = i;
                    int K = sK;
                    kx[K] = s_p0[i]; ky[K] = s_p1[i]; kz[K] = s_p2[i]; kid[K] = i;
                    selp[0] = s_p0[i]; selp[1] = s_p1[i]; selp[2] = s_p2[i];
                    sK = K + 1;
                }
            }
        }
        __syncthreads();
        if (sSel < 0) break;
        float c0 = selp[0], c1 = selp[1], c2 = selp[2];
        #pragma unroll
        for (int j = 0; j < NITER; j++) {
            int n = tid + j * THREADS;
            if (s_conf[n] != -FLT_MAX) {
                float d0 = s_p0[n] - c0, d1 = s_p1[n] - c1, d2 = s_p2[n] - c2;
                float ss = (d0 * d0 + d1 * d1) + d2 * d2;
                if (ss < CUT2) s_conf[n] = -FLT_MAX;
            }
        }
        __syncthreads();
    }

    // ---- Phase 3: per kept pred, first in-range active target; angles (R8) ----
    const int K = sK;
    for (int k = 0; k < K; k++) {
        float q0 = kx[k] * 25.0f, q1 = ky[k] * 25.0f, q2 = kz[k] * 4.0f;
        int best = 0x7fffffff;
        #pragma unroll
        for (int j = 0; j < NITER; j++) {
            int t = tid + j * THREADS;
            if (s_tc[t] > 0.5f) {
                float d0 = s_t0[t] - q0, d1 = s_t1[t] - q1, d2 = s_t2[t] - q2;
                float ss = (d0 * d0 + d1 * d1) + d2 * d2;
                if (ss < CUT2 && t < best) best = t;
            }
        }
        #pragma unroll
        for (int o = 16; o; o >>= 1) {
            int v2 = __shfl_down_sync(0xffffffffu, best, o);
            if (v2 < best) best = v2;
        }
        if (lane == 0) wi[warp] = best;
        __syncthreads();
        if (tid == 0) {
            int bmin = 0x7fffffff;
            for (int w = 0; w < NWARP; w++) if (wi[w] < bmin) bmin = wi[w];
            if (bmin != 0x7fffffff) {
                sTP += 1;
                int i = kid[k];
                const float* p = P + (long long)i * 10;
                const float* t = T + (long long)bmin * 10;
                float ax = p[4], ay = p[5], az = p[6];
                float bx = p[7], by = p[8], bz = p[9];
                float cx = ay * bz - az * by;
                float cy = az * bx - ax * bz;
                float cz = ax * by - ay * bx;
                float tax = t[4], tay = t[5], taz = t[6];
                float tbx = t[7], tby = t[8], tbz = t[9];
                float tcx = tay * tbz - taz * tby;
                float tcy = taz * tbx - tax * tbz;
                float tcz = tax * tby - tay * tbx;
                sAng += row_angle(ax, ay, az, tax, tay, taz)
                      + row_angle(bx, by, bz, tbx, tby, tbz)
                      + row_angle(cx, cy, cz, tcx, tcy, tcz);
            }
        }
        __syncthreads();
    }

    // ---- Phase 4: write outputs ----
    if (tid == 0) {
        float tp = (float)sTP;
        out[b * 3 + 0] = tp;
        out[b * 3 + 1] = (float)K - tp;
        out[b * 3 + 2] = (float)sNTG - tp;
        out[3 * NB + b] = (sTP > 0) ? (sAng / (3.0f * tp)) : 0.0f;
    }
}

extern "C" void kernel_launch(void* const* d_in, const int* in_sizes, int n_in,
                              void* d_out, int out_size) {
    const float* pred = (const float*)d_in[0];
    const float* targ = (const float*)d_in[1];
    float* out = (float*)d_out;
    cudaFuncSetAttribute(mol_kernel, cudaFuncAttributeMaxDynamicSharedMemorySize,
                         SMEM_BYTES);
    mol_kernel<<<NB, THREADS, SMEM_BYTES>>>(pred, targ, out);
}

// round 16
// speedup vs baseline: 1.1633x; 1.1429x over previous
#include <cuda_runtime.h>
#include <math.h>
#include <float.h>
#include <stdint.h>

// Problem constants (from reference): B=8, Z=4, X=32, Y=32, N=4096
#define NPTS   4096
#define NB     8
#define THREADS 512
#define NWARP  (THREADS / 32)
#define NITER  (NPTS / THREADS)   // 8 points per thread, register-resident
#define MAXKEEP 32
#define CUT2   4.0f               // sqrt(ss) < 2  <=>  ss < 4 (exact)

// Dynamic smem: 7 arrays of NPTS floats (pred pos ×3, targ conf+pos ×4)
#define SMEM_BYTES (7 * NPTS * 4)

__device__ __forceinline__ float row_angle(float ax, float ay, float az,
                                           float bx, float by, float bz) {
    float na = sqrtf(ax * ax + ay * ay + az * az);
    float nb = sqrtf(bx * bx + by * by + bz * bz);
    float c = (ax * bx + ay * by + az * bz) / (na * nb);
    c = fminf(1.0f, fmaxf(-1.0f, c));
    return (acosf(c) / 3.14159265358979323846f) * 180.0f;
}

__global__ __launch_bounds__(THREADS, 1)
void mol_kernel(const float* __restrict__ pred,
                const float* __restrict__ targ,
                float* __restrict__ out) {
    extern __shared__ float sm[];
    float* s_p0 = sm;                   // [NPTS] pred pos normalized (broadcast src)
    float* s_p1 = s_p0 + NPTS;
    float* s_p2 = s_p1 + NPTS;
    float* s_tc = s_p2 + NPTS;          // [NPTS] target conf
    float* s_t0 = s_tc + NPTS;          // [NPTS] target pos REAL coords
    float* s_t1 = s_t0 + NPTS;
    float* s_t2 = s_t1 + NPTS;

    __shared__ unsigned long long sMax[MAXKEEP + 1];  // packed pick per round
    __shared__ float wv[NWARP];
    __shared__ int   wi[NWARP];
    __shared__ int   wCnt[NWARP];
    __shared__ int   kid[MAXKEEP];
    __shared__ float kRX[MAXKEEP], kRY[MAXKEEP], kRZ[MAXKEEP];
    __shared__ int   sTP, sNTG;
    __shared__ float sAng;

    const int tid = threadIdx.x;
    const int lane = tid & 31;
    const int warp = tid >> 5;
    const int b = blockIdx.x;
    const float* P = pred + (long long)b * NPTS * 10;
    const float* T = targ + (long long)b * NPTS * 10;

    if (tid <= MAXKEEP) sMax[tid] = 0ull;
    if (tid == 0) { sTP = 0; sAng = 0.0f; }
    __syncthreads();   // sMax init visible before any atomicMax

    // ---- Phase 1: R8 load (strided float2, fully unrolled) ----
    // pred conf+pos kept in REGISTERS; pos mirrored to smem for broadcasts.
    float cf[NITER], px[NITER], py[NITER], pz[NITER];
    int cnt = 0;
    unsigned long long pk = 0ull;
    #pragma unroll
    for (int j = 0; j < NITER; j++) {
        int n = tid + j * THREADS;
        const float* p = P + n * 10;
        const float* t = T + n * 10;
        // 40-byte pitch is 8-byte aligned for every n -> float2 loads legal
        float2 p01 = *(const float2*)p;
        float2 p23 = *(const float2*)(p + 2);
        float2 t01 = *(const float2*)t;
        float2 t23 = *(const float2*)(t + 2);
        float z = (float)(n >> 10), x = (float)((n >> 5) & 31), y = (float)(n & 31);
        float pc = p01.x;
        // sigmoid(c) > 0.5 <=> c > 0 (exact); /4, /32 exact pow2 mults
        cf[j] = (pc > 0.0f) ? pc : -FLT_MAX;
        px[j] = (p01.y + z) * 0.25f;
        py[j] = (p23.x + x) * 0.03125f;
        pz[j] = (p23.y + y) * 0.03125f;
        s_p0[n] = px[j]; s_p1[n] = py[j]; s_p2[n] = pz[j];
        s_tc[n] = t01.x;
        cnt += (t01.x > 0.5f) ? 1 : 0;
        s_t0[n] = ((t01.y + z) * 0.25f) * 25.0f;   // real coords (×25,25,4)
        s_t1[n] = ((t23.x + x) * 0.03125f) * 25.0f;
        s_t2[n] = ((t23.y + y) * 0.03125f) * 4.0f;
        // fold round-0 argmax: conf>0 => float bits order-preserving; tie -> lower n
        if (pc > 0.0f) {
            unsigned long long q = (((unsigned long long)__float_as_uint(pc)) << 32)
                                 | (unsigned long long)(NPTS - n);
            if (q > pk) pk = q;
        }
    }
    #pragma unroll
    for (int o = 16; o; o >>= 1) {
        unsigned long long q = __shfl_down_sync(0xffffffffu, pk, o);
        if (q > pk) pk = q;
        cnt += __shfl_down_sync(0xffffffffu, cnt, o);
    }
    if (lane == 0) {
        wCnt[warp] = cnt;
        if (pk) atomicMax(&sMax[0], pk);
    }
    __syncthreads();
    if (tid == 0) {
        int s = 0;
        for (int w = 0; w < NWARP; w++) s += wCnt[w];
        sNTG = s;
    }

    // ---- Phase 2: register-resident greedy NMS, ONE barrier per round ----
    int K = 0;
    for (int r = 0; r < MAXKEEP; r++) {
        unsigned long long mx = sMax[r];       // written before previous bar
        if (mx == 0ull) break;                 // uniform: no survivors
        K = r + 1;
        int idx = NPTS - (int)(mx & 0xffffffffu);
        float c0 = s_p0[idx], c1 = s_p1[idx], c2 = s_p2[idx];   // LDS broadcast
        if (tid == 0) {
            kid[r] = idx;
            kRX[r] = c0 * 25.0f; kRY[r] = c1 * 25.0f; kRZ[r] = c2 * 4.0f;
        }
        // suppress pick r in registers; fold next-round argmax in same pass
        unsigned long long nxt = 0ull;
        #pragma unroll
        for (int j = 0; j < NITER; j++) {
            if (cf[j] != -FLT_MAX) {
                float d0 = px[j] - c0, d1 = py[j] - c1, d2 = pz[j] - c2;
                float ss = (d0 * d0 + d1 * d1) + d2 * d2;
                if (ss < CUT2) {
                    cf[j] = -FLT_MAX;
                } else {
                    int n = tid + j * THREADS;
                    unsigned long long q =
                        (((unsigned long long)__float_as_uint(cf[j])) << 32)
                        | (unsigned long long)(NPTS - n);
                    if (q > nxt) nxt = q;
                }
            }
        }
        #pragma unroll
        for (int o = 16; o; o >>= 1) {
            unsigned long long q = __shfl_down_sync(0xffffffffu, nxt, o);
            if (q > nxt) nxt = q;
        }
        if (lane == 0 && nxt) atomicMax(&sMax[r + 1], nxt);
        __syncthreads();
    }

    // ---- Phase 3: per kept pred, first in-range active target; angles (R8) ----
    for (int k = 0; k < K; k++) {
        float q0 = kRX[k], q1 = kRY[k], q2 = kRZ[k];
        int best = 0x7fffffff;
        #pragma unroll
        for (int j = 0; j < NITER; j++) {
            int t = tid + j * THREADS;
            if (s_tc[t] > 0.5f) {
                float d0 = s_t0[t] - q0, d1 = s_t1[t] - q1, d2 = s_t2[t] - q2;
                float ss = (d0 * d0 + d1 * d1) + d2 * d2;
                if (ss < CUT2 && t < best) best = t;
            }
        }
        #pragma unroll
        for (int o = 16; o; o >>= 1) {
            int v2 = __shfl_down_sync(0xffffffffu, best, o);
            if (v2 < best) best = v2;
        }
        if (lane == 0) wi[warp] = best;
        __syncthreads();
        if (tid == 0) {
            int bmin = 0x7fffffff;
            for (int w = 0; w < NWARP; w++) if (wi[w] < bmin) bmin = wi[w];
            if (bmin != 0x7fffffff) {
                sTP += 1;
                int i = kid[k];
                const float* p = P + (long long)i * 10;
                const float* t = T + (long long)bmin * 10;
                float ax = p[4], ay = p[5], az = p[6];
                float bx = p[7], by = p[8], bz = p[9];
                float cx = ay * bz - az * by;
                float cy = az * bx - ax * bz;
                float cz = ax * by - ay * bx;
                float tax = t[4], tay = t[5], taz = t[6];
                float tbx = t[7], tby = t[8], tbz = t[9];
                float tcx = tay * tbz - taz * tby;
                float tcy = taz * tbx - tax * tbz;
                float tcz = tax * tby - tay * tbx;
                sAng += row_angle(ax, ay, az, tax, tay, taz)
                      + row_angle(bx, by, bz, tbx, tby, tbz)
                      + row_angle(cx, cy, cz, tcx, tcy, tcz);
            }
        }
        __syncthreads();
    }

    // ---- Phase 4: write outputs ----
    if (tid == 0) {
        float tp = (float)sTP;
        out[b * 3 + 0] = tp;
        out[b * 3 + 1] = (float)K - tp;
        out[b * 3 + 2] = (float)sNTG - tp;
        out[3 * NB + b] = (sTP > 0) ? (sAng / (3.0f * tp)) : 0.0f;
    }
}

extern "C" void kernel_launch(void* const* d_in, const int* in_sizes, int n_in,
                              void* d_out, int out_size) {
    const float* pred = (const float*)d_in[0];
    const float* targ = (const float*)d_in[1];
    float* out = (float*)d_out;
    cudaFuncSetAttribute(mol_kernel, cudaFuncAttributeMaxDynamicSharedMemorySize,
                         SMEM_BYTES);
    mol_kernel<<<NB, THREADS, SMEM_BYTES>>>(pred, targ, out);
}